// round 14
// baseline (speedup 1.0000x reference)
#include <cuda_runtime.h>
#include <cuda_fp16.h>

#define HH 360
#define WW 720
#define W2 360
#define HW (HH * WW)
#define BB 8
#define TYS 20
#define NIT (TYS + 6)     // 26
#define NTAB (NIT + 2)    // 28 rows: y0-5 .. y0+TYS+2
#define SEGS 13           // 13*28 = 364 >= 360 float2 cols (wrap, dup writes identical)
#define BANDS (HH / TYS)  // 18
#define NSTEPS 20
#define FULLM 0xffffffffu

// Scratch (allocation-free: __device__ globals).
__device__ __half g_hA[BB * HW];          // fp16 T ping
__device__ __half g_hB[BB * HW];          // fp16 T pong
__device__ unsigned int g_uvm[BB * HW];   // half2(u*m, v*m) per scalar point
__device__ __half g_ms[HW];               // half(m * 0.0625), 2D (batch-shared)

__device__ __forceinline__ float2 f2z() { return make_float2(0.f, 0.f); }
__device__ __forceinline__ int rclamp(int r) { return min(max(r, 0), HH - 1); }

// ---- prologue: pack u*m, v*m, m/16 (fp16) and convert input T -> fp16 ping
__global__ void pack_kernel(const float* __restrict__ T,
                            const float* __restrict__ u,
                            const float* __restrict__ v,
                            const float* __restrict__ m)
{
    const int stride = gridDim.x * blockDim.x;
    for (int j = blockIdx.x * blockDim.x + threadIdx.x; j < HW; j += stride) {
        const float mm = m[j];
        g_ms[j] = __float2half_rn(mm * 0.0625f);
#pragma unroll
        for (int b = 0; b < BB; ++b) {
            const int i = b * HW + j;
            const __half2 p = __floats2half2_rn(u[i] * mm, v[i] * mm);
            g_uvm[i] = *(const unsigned int*)&p;
            g_hA[i] = __float2half_rn(T[i]);
        }
    }
}

// advection + horizontal (1,2,1) for 2 scalar cols at 'row'
template <bool IN>
__device__ __forceinline__ float2 adv_h(
    const float2 Fm, const float2 Fc, const float2 Fp,
    const uint2 uvm, const float iD, const int row,
    const float sdyD, const float s2dyD, const bool zL, const bool zR)
{
    float dty0, dty1;
    if (IN) {
        dty0 = (Fp.x - Fm.x) * s2dyD;
        dty1 = (Fp.y - Fm.y) * s2dyD;
    } else {
        const float cA = (row == 0) ? sdyD  : ((row == HH - 1) ? 0.f   : s2dyD);
        const float cB = (row == 0) ? -sdyD : ((row == HH - 1) ? sdyD  : 0.f);
        const float cC = (row == 0) ? 0.f   : ((row == HH - 1) ? -sdyD : -s2dyD);
        dty0 = cA * Fp.x + cB * Fc.x + cC * Fm.x;
        dty1 = cA * Fp.y + cB * Fc.y + cC * Fm.y;
    }
    const float lf = __shfl_up_sync(FULLM, Fc.y, 1);
    const float rt = __shfl_down_sync(FULLM, Fc.x, 1);
    const float2 uv0 = __half22float2(*(const __half2*)&uvm.x);
    const float2 uv1 = __half22float2(*(const __half2*)&uvm.y);
    const float A0 = Fc.x - (uv0.x * ((Fc.y - lf) * iD) + uv0.y * dty0);
    const float A1 = Fc.y - (uv1.x * ((rt - Fc.x) * iD) + uv1.y * dty1);
    float Am = __shfl_up_sync(FULLM, A1, 1);
    float Ap = __shfl_down_sync(FULLM, A0, 1);
    Am = zL ? 0.f : Am;
    Ap = zR ? 0.f : Ap;
    float2 h;
    h.x = Am + 2.f * A0 + A1;
    h.y = A0 + 2.f * A1 + Ap;
    if (!IN && !(row >= 0 && row < HH)) { h.x = 0.f; h.y = 0.f; }
    return h;
}

__device__ __forceinline__ float2 vfilt(
    const float2 ha, const float2 hb, const float2 hc,
    const __half2 ms, const bool valid)
{
    const float2 m = __half22float2(ms);
    float2 F;
    F.x = (ha.x + 2.f * hb.x + hc.x) * m.x;
    F.y = (ha.y + 2.f * hb.y + hc.y) * m.y;
    if (!valid) { F.x = 0.f; F.y = 0.f; }
    return F;
}

// Two fused timesteps; T stored fp16 between launches; optional fp32 final out.
template <bool IN, bool F32OUT>
__device__ __forceinline__ void run_band(
    const __half2* __restrict__ Tb, const uint2* __restrict__ Ab,
    const __half2* __restrict__ Mb, void* __restrict__ Obv,
    const float tabI,
    const int y0, const int c, const bool emitl, const bool zL, const bool zR,
    const float sdyD, const float s2dyD)
{
    float2 T0, T1;
    __half2 TPf1, TPf2;
    uint2  aPf1, aPf2;
    __half2 mPf1, mPf2;
    {
        const int r0 = IN ? (y0 - 4) : rclamp(y0 - 4);
        const int r1 = IN ? (y0 - 3) : rclamp(y0 - 3);
        const int r2 = IN ? (y0 - 2) : rclamp(y0 - 2);
        const int r3 = IN ? (y0 - 1) : rclamp(y0 - 1);
        T0   = __half22float2(Tb[r0 * W2 + c]);
        T1   = __half22float2(Tb[r1 * W2 + c]);
        TPf1 = Tb[r2 * W2 + c];
        TPf2 = Tb[r3 * W2 + c];
        aPf1 = Ab[r1 * W2 + c];
        aPf2 = Ab[r2 * W2 + c];
        mPf1 = Mb[r1 * W2 + c];
        mPf2 = Mb[r2 * W2 + c];
    }

    float2 h1a = f2z(), h1b = f2z(), h1c = f2z();
    float2 F1a = f2z(), F1b = f2z(), F1c = f2z();
    float2 h2a = f2z(), h2b = f2z(), h2c = f2z();
    uint2  aR0 = make_uint2(0,0), aR1 = aR0, aR2 = aR0;
    __half2 z16 = __floats2half2_rn(0.f, 0.f);
    __half2 mR0 = z16, mR1 = z16, mR2 = z16, mR3 = z16;

#pragma unroll
    for (int k = 0; k < NIT; ++k) {
        const int a = y0 - 3 + k;       // step-1 advection row

        // ring shifts (renamed by full unroll)
        mR3 = mR2; mR2 = mR1; mR1 = mR0; mR0 = mPf1; mPf1 = mPf2;
        aR2 = aR1; aR1 = aR0; aR0 = aPf1; aPf1 = aPf2;
        const float2 T2 = __half22float2(TPf1);  TPf1 = TPf2;

        // 2-deep prefetch (T: a+3, uvm/ms: a+2)
        {
            const int rT = IN ? (a + 3) : rclamp(a + 3);
            const int rU = IN ? (a + 2) : rclamp(a + 2);
            TPf2 = Tb[rT * W2 + c];
            aPf2 = Ab[rU * W2 + c];
            mPf2 = Mb[rU * W2 + c];
        }

        // ---- stage 1: step-1 advection + h at row a
        h1a = h1b; h1b = h1c;
        {
            const float iA = __shfl_sync(FULLM, tabI, k + 2);
            h1c = adv_h<IN>(T0, T1, T2, aR0, iA, a, sdyD, s2dyD, zL, zR);
        }

        // ---- stage 2: step-1 vfilter -> F1 at row f = a-1
        F1a = F1b; F1b = F1c;
        if (k >= 2)
            F1c = vfilt(h1a, h1b, h1c, mR1,
                        IN ? true : ((unsigned)(a - 1) < (unsigned)HH));

        // ---- stage 3: step-2 advection + h at row g = a-2
        h2a = h2b; h2b = h2c;
        if (k >= 4) {
            const float iG = __shfl_sync(FULLM, tabI, k);
            h2c = adv_h<IN>(F1a, F1b, F1c, aR2, iG, a - 2, sdyD, s2dyD, zL, zR);
        }

        // ---- stage 4: step-2 vfilter -> emit row e = a-3
        if (k >= 6) {
            if (emitl) {
                const int e = a - 3;        // in [y0, y0+TYS)
                const float2 o = vfilt(h2a, h2b, h2c, mR3, true);
                if (F32OUT)
                    ((float2*)Obv)[e * W2 + c] = o;
                else
                    ((__half2*)Obv)[e * W2 + c] = __floats2half2_rn(o.x, o.y);
            }
        }

        T0 = T1; T1 = T2;
    }
}

template <bool F32OUT>
__device__ __forceinline__ void step_kernel_body(
    const __half* Tin, void* Tout, const float* lat, const float* lon)
{
    const int lane = threadIdx.x;
    const int ws   = blockIdx.x;
    const int seg  = ws % SEGS;
    const int rem  = ws / SEGS;
    const int band = rem % BANDS;
    const int b    = rem / BANDS;
    const int y0   = band * TYS;

    // lane -> float2 column (wrapped). Lanes 2..29 emit.
    int c = seg * 28 - 2 + lane;
    c += (c < 0) ? W2 : 0;
    c -= (c >= W2) ? W2 : 0;
    const bool emitl = (lane >= 2) && (lane <= 29);
    const bool zL = (c == 0);
    const bool zR = (c == W2 - 1);

    const float DEG2RAD = 0.017453292519943295f;
    const float RE = 6371000.0f, DTC = 600.0f;
    const float dlat = lat[1] - lat[0];
    const float dlon = lon[1] - lon[0];
    const float dy   = RE * DEG2RAD * fabsf(dlat);
    const float sgn  = (dlat > 0.f) ? 1.f : -1.f;
    const float sdyD  = DTC * sgn / dy;
    const float s2dyD = DTC * sgn / (2.f * dy);
    const float xden = 2.f * RE * DEG2RAD * dlon;

    // per-lane DT/(2dx) table: lane i holds row y0-5+i (clamped)
    const int tr = rclamp(y0 - 5 + min(lane, NTAB - 1));
    const float tabI = __fdividef(DTC, xden * __cosf(lat[tr] * DEG2RAD));

    const __half2* Tb = (const __half2*)(Tin + (size_t)b * HW);
    const uint2*   Ab = (const uint2*)(g_uvm + (size_t)b * HW);
    const __half2* Mb = (const __half2*)g_ms;
    void* Ob = F32OUT ? (void*)((float*)Tout + (size_t)b * HW)
                      : (void*)((__half*)Tout + (size_t)b * HW);

    if (band > 0 && band < BANDS - 1)
        run_band<true , F32OUT>(Tb, Ab, Mb, Ob, tabI, y0, c, emitl, zL, zR, sdyD, s2dyD);
    else
        run_band<false, F32OUT>(Tb, Ab, Mb, Ob, tabI, y0, c, emitl, zL, zR, sdyD, s2dyD);
}

__global__ __launch_bounds__(32) void ocean_step2_h(
    const __half* __restrict__ Tin, __half* __restrict__ Tout,
    const float* __restrict__ lat, const float* __restrict__ lon)
{
    step_kernel_body<false>(Tin, Tout, lat, lon);
}

__global__ __launch_bounds__(32) void ocean_step2_f(
    const __half* __restrict__ Tin, float* __restrict__ Tout,
    const float* __restrict__ lat, const float* __restrict__ lon)
{
    step_kernel_body<true>(Tin, Tout, lat, lon);
}

extern "C" void kernel_launch(void* const* d_in, const int* in_sizes, int n_in,
                              void* d_out, int out_size)
{
    const float* T    = (const float*)d_in[0];
    const float* ug   = (const float*)d_in[1];
    const float* vg   = (const float*)d_in[2];
    const float* lat  = (const float*)d_in[3];
    const float* lon  = (const float*)d_in[4];
    const float* mask = (const float*)d_in[5];
    float* out = (float*)d_out;

    __half *hA = nullptr, *hB = nullptr;
    cudaGetSymbolAddress((void**)&hA, g_hA);
    cudaGetSymbolAddress((void**)&hB, g_hB);

    pack_kernel<<<296, 256>>>(T, ug, vg, mask);

    const int nblocks = SEGS * BANDS * BB;   // 13*18*8 = 1872 one-warp blocks
    dim3 grid(nblocks);
    dim3 block(32);

    // 9 fp16->fp16 launches + 1 fp16->fp32 final = 20 steps
    const __half* cur = hA;
    for (int p = 0; p < 9; ++p) {
        __half* dst = (p & 1) ? hA : hB;
        ocean_step2_h<<<grid, block>>>(cur, dst, lat, lon);
        cur = dst;
    }
    ocean_step2_f<<<grid, block>>>(cur, out, lat, lon);
}

// round 16
// speedup vs baseline: 1.1174x; 1.1174x over previous
#include <cuda_runtime.h>
#include <cuda_fp16.h>

#define HH 360
#define WW 720
#define W2 360
#define HW (HH * WW)
#define BB 8
#define TYS 15
#define NIT (TYS + 7)     // 22
#define SEGS 13           // 13*28 = 364 >= 360 float2 cols (wrap, dup writes identical)
#define BANDS (HH / TYS)  // 24
#define NSTEPS 20
#define FULLM 0xffffffffu

// Scratch (allocation-free: __device__ globals).
__device__ float g_bufA[BB * HW];
__device__ float g_bufB[BB * HW];
__device__ unsigned int g_uvm[BB * HW];   // half2(u*m, v*m) per scalar point
__device__ __half g_ms[HW];               // half(m * 0.0625), 2D (batch-shared)

__device__ __forceinline__ float2 f2z() { return make_float2(0.f, 0.f); }
__device__ __forceinline__ int rclamp(int r) { return min(max(r, 0), HH - 1); }

// ---- prologue: pack u*m, v*m (fp16) and m*0.0625 (fp16), once per replay
__global__ void pack_kernel(const float* __restrict__ u,
                            const float* __restrict__ v,
                            const float* __restrict__ m)
{
    const int stride = gridDim.x * blockDim.x;
    for (int j = blockIdx.x * blockDim.x + threadIdx.x; j < HW; j += stride) {
        const float mm = m[j];
        g_ms[j] = __float2half_rn(mm * 0.0625f);
#pragma unroll
        for (int b = 0; b < BB; ++b) {
            const int i = b * HW + j;
            const __half2 p = __floats2half2_rn(u[i] * mm, v[i] * mm);
            g_uvm[i] = *(const unsigned int*)&p;
        }
    }
}

// advection + horizontal (1,2,1) for 2 scalar cols at 'row'
template <bool IN>
__device__ __forceinline__ float2 adv_h(
    const float2 Fm, const float2 Fc, const float2 Fp,
    const uint2 uvm, const float iD, const int row,
    const float sdyD, const float s2dyD, const bool zL, const bool zR)
{
    float dty0, dty1;
    if (IN) {
        dty0 = (Fp.x - Fm.x) * s2dyD;
        dty1 = (Fp.y - Fm.y) * s2dyD;
    } else {
        const float cA = (row == 0) ? sdyD  : ((row == HH - 1) ? 0.f   : s2dyD);
        const float cB = (row == 0) ? -sdyD : ((row == HH - 1) ? sdyD  : 0.f);
        const float cC = (row == 0) ? 0.f   : ((row == HH - 1) ? -sdyD : -s2dyD);
        dty0 = cA * Fp.x + cB * Fc.x + cC * Fm.x;
        dty1 = cA * Fp.y + cB * Fc.y + cC * Fm.y;
    }
    const float lf = __shfl_up_sync(FULLM, Fc.y, 1);
    const float rt = __shfl_down_sync(FULLM, Fc.x, 1);
    const float2 uv0 = __half22float2(*(const __half2*)&uvm.x);
    const float2 uv1 = __half22float2(*(const __half2*)&uvm.y);
    const float A0 = Fc.x - (uv0.x * ((Fc.y - lf) * iD) + uv0.y * dty0);
    const float A1 = Fc.y - (uv1.x * ((rt - Fc.x) * iD) + uv1.y * dty1);
    float Am = __shfl_up_sync(FULLM, A1, 1);
    float Ap = __shfl_down_sync(FULLM, A0, 1);
    Am = zL ? 0.f : Am;
    Ap = zR ? 0.f : Ap;
    float2 h;
    h.x = Am + 2.f * A0 + A1;
    h.y = A0 + 2.f * A1 + Ap;
    if (!IN && !(row >= 0 && row < HH)) { h.x = 0.f; h.y = 0.f; }
    return h;
}

__device__ __forceinline__ float2 vfilt(
    const float2 ha, const float2 hb, const float2 hc,
    const __half2 ms, const bool valid)
{
    const float2 m = __half22float2(ms);
    float2 F;
    F.x = (ha.x + 2.f * hb.x + hc.x) * m.x;
    F.y = (ha.y + 2.f * hb.y + hc.y) * m.y;
    if (!valid) { F.x = 0.f; F.y = 0.f; }
    return F;
}

// Two fused timesteps, DECOUPLED pipeline: stage3/stage4 trail stage1/stage2
// by one extra row. At stage3 of iteration k the F1 ring holds rows
// a-2 (F1_1, newest), a-3 (F1_2), a-4 (F1_3) — all written in PREVIOUS
// iterations, so the two advection chains are independent. Emit row = a-4.
template <bool IN>
__device__ __forceinline__ void run_band(
    const float2* __restrict__ Tb, const uint2* __restrict__ Ab,
    const __half2* __restrict__ Mb, float2* __restrict__ Ob,
    const float tabI,
    const int y0, const int c, const bool emitl, const bool zL, const bool zR,
    const float sdyD, const float s2dyD)
{
    float2 T0, T1, TPf1, TPf2;
    uint2  aPf1, aPf2;
    __half2 mPf1, mPf2;
    {
        const int r0 = IN ? (y0 - 4) : rclamp(y0 - 4);
        const int r1 = IN ? (y0 - 3) : rclamp(y0 - 3);
        const int r2 = IN ? (y0 - 2) : rclamp(y0 - 2);
        const int r3 = IN ? (y0 - 1) : rclamp(y0 - 1);
        T0   = Tb[r0 * W2 + c];
        T1   = Tb[r1 * W2 + c];
        TPf1 = Tb[r2 * W2 + c];
        TPf2 = Tb[r3 * W2 + c];
        aPf1 = Ab[r1 * W2 + c];
        aPf2 = Ab[r2 * W2 + c];
        mPf1 = Mb[r1 * W2 + c];
        mPf2 = Mb[r2 * W2 + c];
    }

    float2 h1a = f2z(), h1b = f2z(), h1c = f2z();
    // F1 ring, 3 deep: F1_1 = newest (row a-2 at stage3-time), F1_3 = oldest
    float2 F1_1 = f2z(), F1_2 = f2z(), F1_3 = f2z();
    float2 h2a = f2z(), h2b = f2z(), h2c = f2z();
    // uvm ring rows a..a-3 ; ms ring rows a..a-4
    uint2  aR0 = make_uint2(0,0), aR1 = aR0, aR2 = aR0, aR3 = aR0;
    __half2 z16 = __floats2half2_rn(0.f, 0.f);
    __half2 mR0 = z16, mR1 = z16, mR2 = z16, mR3 = z16, mR4 = z16;

#pragma unroll
    for (int k = 0; k < NIT; ++k) {
        const int a = y0 - 3 + k;       // step-1 advection row

        // ring shifts (renamed by full unroll)
        mR4 = mR3; mR3 = mR2; mR2 = mR1; mR1 = mR0; mR0 = mPf1; mPf1 = mPf2;
        aR3 = aR2; aR2 = aR1; aR1 = aR0; aR0 = aPf1; aPf1 = aPf2;
        const float2 T2 = TPf1;  TPf1 = TPf2;

        // 2-deep prefetch (T: a+3, uvm/ms: a+2)
        {
            const int rT = IN ? (a + 3) : rclamp(a + 3);
            const int rU = IN ? (a + 2) : rclamp(a + 2);
            TPf2 = Tb[rT * W2 + c];
            aPf2 = Ab[rU * W2 + c];
            mPf2 = Mb[rU * W2 + c];
        }

        // ---- stage 3: step-2 advection + h at row g = a-3, from F1 rows
        //      a-4 (F1_3), a-3 (F1_2), a-2 (F1_1) — all from prior iterations
        h2a = h2b; h2b = h2c;
        if (k >= 5) {
            const float iG = __shfl_sync(FULLM, tabI, k);   // row a-3 = y0-6+k
            h2c = adv_h<IN>(F1_3, F1_2, F1_1, aR3, iG, a - 3, sdyD, s2dyD, zL, zR);
        }

        // ---- stage 4: step-2 vfilter -> emit row e = a-4
        if (k >= 7) {
            if (emitl) {
                const int e = a - 4;        // in [y0, y0+TYS)
                Ob[e * W2 + c] = vfilt(h2a, h2b, h2c, mR4, true);
            }
        }

        // ---- stage 1: step-1 advection + h at row a
        h1a = h1b; h1b = h1c;
        {
            const float iA = __shfl_sync(FULLM, tabI, k + 3);  // row a = y0-6+(k+3)
            h1c = adv_h<IN>(T0, T1, T2, aR0, iA, a, sdyD, s2dyD, zL, zR);
        }

        // ---- stage 2: step-1 vfilter -> F1 at row f = a-1
        F1_3 = F1_2; F1_2 = F1_1;
        if (k >= 2)
            F1_1 = vfilt(h1a, h1b, h1c, mR1,
                         IN ? true : ((unsigned)(a - 1) < (unsigned)HH));

        T0 = T1; T1 = T2;
    }
}

// One warp per block.
__global__ __launch_bounds__(32) void ocean_step2(
    const float* __restrict__ Tin, float* __restrict__ Tout,
    const float* __restrict__ lat, const float* __restrict__ lon)
{
    const int lane = threadIdx.x;
    const int ws   = blockIdx.x;
    const int seg  = ws % SEGS;
    const int rem  = ws / SEGS;
    const int band = rem % BANDS;
    const int b    = rem / BANDS;
    const int y0   = band * TYS;

    // lane -> float2 column (wrapped). Lanes 2..29 emit.
    int c = seg * 28 - 2 + lane;
    c += (c < 0) ? W2 : 0;
    c -= (c >= W2) ? W2 : 0;
    const bool emitl = (lane >= 2) && (lane <= 29);
    const bool zL = (c == 0);
    const bool zR = (c == W2 - 1);

    const float DEG2RAD = 0.017453292519943295f;
    const float RE = 6371000.0f, DTC = 600.0f;
    const float dlat = lat[1] - lat[0];
    const float dlon = lon[1] - lon[0];
    const float dy   = RE * DEG2RAD * fabsf(dlat);
    const float sgn  = (dlat > 0.f) ? 1.f : -1.f;
    const float sdyD  = DTC * sgn / dy;
    const float s2dyD = DTC * sgn / (2.f * dy);
    const float xden = 2.f * RE * DEG2RAD * dlon;

    // per-lane DT/(2dx) table: lane i holds row y0-6+i (clamped); read via shfl
    const int tr = rclamp(y0 - 6 + lane);
    const float tabI = __fdividef(DTC, xden * __cosf(lat[tr] * DEG2RAD));

    const float2*  Tb = (const float2*)(Tin + (size_t)b * HW);
    const uint2*   Ab = (const uint2*)(g_uvm + (size_t)b * HW);
    const __half2* Mb = (const __half2*)g_ms;
    float2*        Ob = (float2*)(Tout + (size_t)b * HW);

    if (band > 0 && band < BANDS - 1)
        run_band<true >(Tb, Ab, Mb, Ob, tabI, y0, c, emitl, zL, zR, sdyD, s2dyD);
    else
        run_band<false>(Tb, Ab, Mb, Ob, tabI, y0, c, emitl, zL, zR, sdyD, s2dyD);
}

extern "C" void kernel_launch(void* const* d_in, const int* in_sizes, int n_in,
                              void* d_out, int out_size)
{
    const float* T    = (const float*)d_in[0];
    const float* ug   = (const float*)d_in[1];
    const float* vg   = (const float*)d_in[2];
    const float* lat  = (const float*)d_in[3];
    const float* lon  = (const float*)d_in[4];
    const float* mask = (const float*)d_in[5];
    float* out = (float*)d_out;

    float *bufA = nullptr, *bufB = nullptr;
    cudaGetSymbolAddress((void**)&bufA, g_bufA);
    cudaGetSymbolAddress((void**)&bufB, g_bufB);

    pack_kernel<<<296, 256>>>(ug, vg, mask);

    const int nblocks = SEGS * BANDS * BB;   // 13*24*8 = 2496 one-warp blocks
    dim3 grid(nblocks);
    dim3 block(32);

    const float* cur = T;
    const int npairs = NSTEPS / 2;           // 10 fused launches
    for (int p = 0; p < npairs; ++p) {
        float* dst = (p == npairs - 1) ? out : ((p & 1) ? bufB : bufA);
        ocean_step2<<<grid, block>>>(cur, dst, lat, lon);
        cur = dst;
    }
}